// round 7
// baseline (speedup 1.0000x reference)
#include <cuda_runtime.h>

// Problem constants (fixed shapes from the reference setup)
#define NB   16      // batch
#define NT   128     // time
#define NHWC 25088   // 56*56*8 floats per frame
#define NS4  6272    // NHWC / 4 (float4 strips per frame)
#define NC   8       // channels
#define KCH  4       // time chunks
#define TC   (NT / KCH)             // 32 frames per chunk
#define BT   224                    // block threads; NS4 = 28 * 224 exactly
#define NW   (BT / 32)              // 7 warps
#define NBLK_S (NS4 / BT)           // 28 blocks over the spatial strip
#define SLOTS_PER_B (KCH * NBLK_S)  // 112 blocks per batch
#define NBLKS  (NB * SLOTS_PER_B)   // 1792 total blocks
#define NFLD   17                   // 8 act + 8 tot + 1 ttv

// Scratch (no device allocation allowed -> __device__ globals).
// FIELD-MAJOR partials: g_part[field][slot]; coalesced tail reads.
// Every block writes all its fields every launch => no zeroing needed.
// Counters self-reset each launch => graph-replay deterministic.
__device__ float        g_part[NFLD][NBLKS];
__device__ float        g_batch[NB][NFLD];
__device__ unsigned int g_ctr_b[NB];
__device__ unsigned int g_ctr2;

__global__ __launch_bounds__(BT) void fused_kernel(const float4* __restrict__ x,
                                                   const int*   __restrict__ length,
                                                   const float* __restrict__ count,
                                                   float*       __restrict__ out) {
    const int s4    = blockIdx.x * BT + threadIdx.x;   // always < NS4
    const int b     = blockIdx.z;
    const int chunk = blockIdx.y;
    const int len   = __ldg(&length[b]);
    const int t0    = chunk * TC;
    const float4* base = x + (size_t)b * NT * NS4 + s4;

    float ax = 0.f, ay = 0.f, az = 0.f, aw = 0.f;   // active sums (4 channels)
    float tx = 0.f, ty = 0.f, tz = 0.f, tw = 0.f;   // total sums
    float ttv = 0.f;
    float px = 0.f, py = 0.f, pz = 0.f, pw = 0.f;   // previous masked frame

    if (t0 > 0 && (t0 - 1) < len) {
        float4 p = __ldcs(&base[(size_t)(t0 - 1) * NS4]);
        px = p.x; py = p.y; pz = p.z; pw = p.w;
    }
    #pragma unroll 8
    for (int t = t0; t < t0 + TC; ++t) {
        float4 v = __ldcs(&base[(size_t)t * NS4]);
        tx += v.x; ty += v.y; tz += v.z; tw += v.w;
        float cx, cy, cz, cw;
        if (t < len) {
            cx = v.x; cy = v.y; cz = v.z; cw = v.w;
            ax += v.x; ay += v.y; az += v.z; aw += v.w;
        } else {
            cx = 0.f; cy = 0.f; cz = 0.f; cw = 0.f;
        }
        if (t > 0) {   // skip only the global t=0 (chunk 0, first iter)
            ttv += fabsf(cx - px) + fabsf(cy - py) + fabsf(cz - pz) + fabsf(cw - pw);
        }
        px = cx; py = cy; pz = cz; pw = cw;
    }

    // --- block reduction ---
    #pragma unroll
    for (int m = 16; m >= 1; m >>= 1)
        ttv += __shfl_xor_sync(0xffffffffu, ttv, m);
    // Parity-preserving reduce: even lanes hold channels 0-3, odd lanes 4-7
    #pragma unroll
    for (int m = 2; m <= 16; m <<= 1) {
        ax += __shfl_xor_sync(0xffffffffu, ax, m);
        ay += __shfl_xor_sync(0xffffffffu, ay, m);
        az += __shfl_xor_sync(0xffffffffu, az, m);
        aw += __shfl_xor_sync(0xffffffffu, aw, m);
        tx += __shfl_xor_sync(0xffffffffu, tx, m);
        ty += __shfl_xor_sync(0xffffffffu, ty, m);
        tz += __shfl_xor_sync(0xffffffffu, tz, m);
        tw += __shfl_xor_sync(0xffffffffu, tw, m);
    }

    __shared__ float sh_a[NW][NC];
    __shared__ float sh_t[NW][NC];
    __shared__ float sh_v[NW];
    const int w = threadIdx.x >> 5, lane = threadIdx.x & 31;
    if (lane == 0) {
        sh_a[w][0] = ax; sh_a[w][1] = ay; sh_a[w][2] = az; sh_a[w][3] = aw;
        sh_t[w][0] = tx; sh_t[w][1] = ty; sh_t[w][2] = tz; sh_t[w][3] = tw;
        sh_v[w] = ttv;
    } else if (lane == 1) {
        sh_a[w][4] = ax; sh_a[w][5] = ay; sh_a[w][6] = az; sh_a[w][7] = aw;
        sh_t[w][4] = tx; sh_t[w][5] = ty; sh_t[w][6] = tz; sh_t[w][7] = tw;
    }
    __syncthreads();

    const int slot = (b * KCH + chunk) * NBLK_S + blockIdx.x;
    if (threadIdx.x < NC) {
        const int c = threadIdx.x;
        float sa = 0.f, st = 0.f;
        #pragma unroll
        for (int w2 = 0; w2 < NW; ++w2) { sa += sh_a[w2][c]; st += sh_t[w2][c]; }
        g_part[c][slot]      = sa;
        g_part[NC + c][slot] = st;
    } else if (threadIdx.x == NC) {
        float s = 0.f;
        #pragma unroll
        for (int w2 = 0; w2 < NW; ++w2) s += sh_v[w2];
        g_part[16][slot] = s;
    }

    // ---- level-1 tail: last block of THIS batch reduces the batch's rows ----
    __threadfence();   // release partial stores
    __shared__ bool s_last;
    if (threadIdx.x == 0)
        s_last = (atomicAdd(&g_ctr_b[b], 1u) == SLOTS_PER_B - 1);
    __syncthreads();
    if (!s_last) return;

    // Coalesced: field-major rows, 112 consecutive slots for this batch.
    for (int r = w; r < NFLD; r += NW) {
        const float* p = &g_part[r][b * SLOTS_PER_B + lane];
        float acc = __ldcg(&p[0]) + __ldcg(&p[32]) + __ldcg(&p[64]);
        if (lane < 16) acc += __ldcg(&p[96]);
        #pragma unroll
        for (int m = 16; m >= 1; m >>= 1)
            acc += __shfl_xor_sync(0xffffffffu, acc, m);
        if (lane == 0) g_batch[b][r] = acc;
    }
    __threadfence();   // release g_batch stores
    __syncthreads();

    // ---- level-2 tail: last batch-finisher computes the outputs ----
    if (threadIdx.x == 0) {
        g_ctr_b[b] = 0;   // self-reset for next graph replay
        s_last = (atomicAdd(&g_ctr2, 1u) == NB - 1);
    }
    __syncthreads();
    if (!s_last) return;
    if (threadIdx.x == 0) g_ctr2 = 0;

    if (w == 0) {
        float tv = (lane < NB) ? __ldcg(&g_batch[lane][16]) : 0.f;
        #pragma unroll
        for (int m = 16; m >= 1; m >>= 1)
            tv += __shfl_xor_sync(0xffffffffu, tv, m);
        if (lane < NB) {
            const int bb = lane;
            float ah = 0.f, bh = 0.f;
            #pragma unroll
            for (int c = 0; c < NC; ++c) {
                const float aa = __ldcg(&g_batch[bb][c]);
                const float tt = __ldcg(&g_batch[bb][NC + c]);
                float e  = aa - __ldg(&count[bb * NC + c]);
                float ae = fabsf(e);
                ah += (ae <= 1.f) ? 0.5f * e * e : (ae - 0.5f);
                float eb  = tt - aa;
                float aeb = fabsf(eb);
                bh += (aeb <= 1.f) ? 0.5f * eb * eb : (aeb - 0.5f);
            }
            out[bb] = ah * (1.f / NC) + bh * (1.f / NC) + tv * 0.1f;
        }
    }
}

extern "C" void kernel_launch(void* const* d_in, const int* in_sizes, int n_in,
                              void* d_out, int out_size) {
    const float* cam    = (const float*)d_in[0];
    const float* count  = (const float*)d_in[1];
    const int*   length = (const int*)d_in[2];
    float*       out    = (float*)d_out;

    dim3 grid(NBLK_S, KCH, NB);
    fused_kernel<<<grid, BT>>>((const float4*)cam, length, count, out);
}